// round 15
// baseline (speedup 1.0000x reference)
#include <cuda_runtime.h>
#include <cuda_fp16.h>
#include <math.h>

#define N_TX   100000
#define N_ADDR 100000
#define E_NUM  1000000
#define G_NUM  128

#define SCAN_ELEMS_PER_BLOCK 1024
#define SCAN_BLOCKS ((N_TX + SCAN_ELEMS_PER_BLOCK - 1) / SCAN_ELEMS_PER_BLOCK)  // 98

// ---------------- scratch ----------------------------------------------------------
__device__ float g_At[64 * 68];
__device__ float g_b_addr[64];
__device__ float g_U_tx[65 * 4];
__device__ float g_v_tx[4];
__device__ __half g_z_half[N_ADDR * 64];   // z_addr in fp16 (accumulation stays fp32)
__device__ float g_alpha_src[N_ADDR * 4];
__device__ float g_alpha_dst[N_TX * 4];
__device__ float g_pool[G_NUM * 64];
__device__ float g_cnt[G_NUM];
// CSR scratch
__device__ int g_deg[N_TX];
__device__ int g_off[N_TX + 1];
__device__ int g_woff[N_TX];
__device__ int g_csr_src[E_NUM];
__device__ int g_bsum[SCAN_BLOCKS];

__device__ __forceinline__ float leaky(float x) { return x > 0.f ? x : 0.2f * x; }

__device__ __forceinline__ void red_add_v2(float* addr, float2 v) {
    asm volatile("red.global.add.v2.f32 [%0], {%1, %2};"
                 :: "l"(addr), "f"(v.x), "f"(v.y) : "memory");
}

// ---------------- kernel 1: fold weights -------------------------------------------
__global__ void prep_kernel(const float* __restrict__ Wp_tx, const float* __restrict__ bp_tx,
                            const float* __restrict__ Wp_addr, const float* __restrict__ bp_addr,
                            const float* __restrict__ Wh_tx, const float* __restrict__ bh_tx,
                            const float* __restrict__ Wh_addr, const float* __restrict__ bh_addr,
                            const float* __restrict__ att_dst_at) {
    __shared__ float t[64 * 4];
    int tid = threadIdx.x;
    for (int idx = tid; idx < 64 * 4; idx += blockDim.x) {
        int j = idx >> 2, h = idx & 3;
        float s = 0.f;
        for (int d = 0; d < 16; d++) s += Wh_tx[j * 64 + h * 16 + d] * att_dst_at[h * 16 + d];
        t[j * 4 + h] = s;
    }
    __syncthreads();
    for (int idx = tid; idx < 65 * 4; idx += blockDim.x) {
        int k = idx >> 2, h = idx & 3;
        float s = 0.f;
        for (int j = 0; j < 64; j++) s += Wp_tx[k * 64 + j] * t[j * 4 + h];
        g_U_tx[k * 4 + h] = s;
    }
    if (tid < 4) {
        int h = tid;
        float s = 0.f;
        for (int j = 0; j < 64; j++) s += bp_tx[j] * t[j * 4 + h];
        for (int d = 0; d < 16; d++) s += bh_tx[h * 16 + d] * att_dst_at[h * 16 + d];
        g_v_tx[h] = s;
    }
    for (int idx = tid; idx < 65 * 64; idx += blockDim.x) {
        int k = idx >> 6, c = idx & 63;
        float s = 0.f;
        for (int j = 0; j < 64; j++) s += Wp_addr[k * 64 + j] * Wh_addr[j * 64 + c];
        g_At[c * 68 + k] = s;
    }
    for (int i = tid; i < 64 * 3; i += blockDim.x)
        g_At[(i / 3) * 68 + 65 + (i % 3)] = 0.f;
    for (int c = tid; c < 64; c += blockDim.x) {
        float s = bh_addr[c];
        for (int j = 0; j < 64; j++) s += bp_addr[j] * Wh_addr[j * 64 + c];
        g_b_addr[c] = s;
    }
}

// ---------------- kernel 2: init (zeroing ONLY — no accumulation here) --------------
__global__ void init_kernel() {
    int i = blockIdx.x * blockDim.x + threadIdx.x;
    if (i < N_TX) g_deg[i] = 0;
    if (i < G_NUM * 64) g_pool[i] = 0.f;
    if (i < G_NUM) g_cnt[i] = 0.f;
    if (i == 0) g_off[N_TX] = E_NUM;
}

// ---------------- cnt: per-graph node counts (runs AFTER init, same stream) ---------
__global__ void cnt_kernel(const int* __restrict__ batch_tx) {
    __shared__ int loc[G_NUM];
    int t = threadIdx.x;
    if (t < G_NUM) loc[t] = 0;
    __syncthreads();
    for (int i = blockIdx.x * blockDim.x + t; i < N_TX; i += gridDim.x * blockDim.x)
        atomicAdd(&loc[batch_tx[i]], 1);
    __syncthreads();
    if (t < G_NUM && loc[t] > 0) atomicAdd(&g_cnt[t], (float)loc[t]);
}

// ---------------- kernel 3: alpha_dst (warp per tx node) ---------------------------
__global__ void tx_alpha_kernel(const float* __restrict__ x_tx) {
    __shared__ float U[65 * 4];
    __shared__ float v[4];
    int tid = threadIdx.x;
    for (int i = tid; i < 65 * 4; i += blockDim.x) U[i] = g_U_tx[i];
    if (tid < 4) v[tid] = g_v_tx[tid];
    __syncthreads();
    int warp = (blockIdx.x * blockDim.x + tid) >> 5;
    int lane = tid & 31;
    if (warp >= N_TX) return;
    const float* xr = x_tx + (long long)warp * 65;
    float x0 = xr[lane];
    float x1 = xr[32 + lane];
    float x2 = (lane == 0) ? xr[64] : 0.f;
#pragma unroll
    for (int h = 0; h < 4; h++) {
        float p = x0 * U[lane * 4 + h] + x1 * U[(32 + lane) * 4 + h] + x2 * U[64 * 4 + h];
#pragma unroll
        for (int off = 16; off > 0; off >>= 1) p += __shfl_xor_sync(0xffffffffu, p, off);
        if (lane == h) g_alpha_dst[warp * 4 + h] = p + v[h];
    }
}

// ---------------- kernel 4: z_addr GEMM, A in registers, fp16 z stores --------------
__global__ void __launch_bounds__(256) addr_gemm_kernel(const float* __restrict__ x_addr,
                                                        const float* __restrict__ att_src_at) {
    __shared__ float xs[32][68];
    __shared__ float bs[64];
    __shared__ float att[64];
    int tid = threadIdx.x;
    int col = tid & 63, y = tid >> 6;
    float4 a[17];
    const float4* ap = (const float4*)&g_At[col * 68];
#pragma unroll
    for (int i = 0; i < 17; i++) a[i] = ap[i];
    if (tid < 64) { bs[tid] = g_b_addr[tid]; att[tid] = att_src_at[tid]; }
    for (int i = tid; i < 32 * 3; i += 256) xs[i / 3][65 + (i % 3)] = 0.f;
    __syncthreads();

    int base = blockIdx.x * 128;
#pragma unroll 1
    for (int t = 0; t < 4; t++) {
        int tile0 = base + t * 32;
        for (int i = tid; i < 32 * 65; i += 256) {
            int n = i / 65, k = i - n * 65;
            int node = tile0 + n;
            xs[n][k] = (node < N_ADDR) ? x_addr[(long long)node * 65 + k] : 0.f;
        }
        __syncthreads();
        float acc[8];
#pragma unroll
        for (int n = 0; n < 8; n++) acc[n] = bs[col];
#pragma unroll
        for (int k4 = 0; k4 < 17; k4++) {
            float4 av = a[k4];
#pragma unroll
            for (int n = 0; n < 8; n++) {
                float4 xv = *(const float4*)&xs[y * 8 + n][k4 * 4];
                acc[n] += xv.x * av.x + xv.y * av.y + xv.z * av.z + xv.w * av.w;
            }
        }
#pragma unroll
        for (int n = 0; n < 8; n++) {
            int node = tile0 + y * 8 + n;
            if (node < N_ADDR) {
                g_z_half[node * 64 + col] = __float2half_rn(acc[n]);
                float p = acc[n] * att[col];
#pragma unroll
                for (int off = 8; off > 0; off >>= 1) p += __shfl_xor_sync(0xffffffffu, p, off);
                if ((col & 15) == 0) g_alpha_src[node * 4 + (col >> 4)] = p;
            }
        }
        __syncthreads();
    }
}

// ---------------- CSR build ---------------------------------------------------------
__global__ void hist_kernel(const int* __restrict__ edge) {
    int e = blockIdx.x * blockDim.x + threadIdx.x;
    if (e >= E_NUM) return;
    atomicAdd(&g_deg[edge[E_NUM + e]], 1);
}

__global__ void scan_sum_kernel() {
    __shared__ int wsum[8];
    int t = threadIdx.x;
    int base = blockIdx.x * SCAN_ELEMS_PER_BLOCK + t * 4;
    int s = 0;
#pragma unroll
    for (int j = 0; j < 4; j++) {
        int i = base + j;
        if (i < N_TX) s += g_deg[i];
    }
#pragma unroll
    for (int off = 16; off > 0; off >>= 1) s += __shfl_xor_sync(0xffffffffu, s, off);
    if ((t & 31) == 0) wsum[t >> 5] = s;
    __syncthreads();
    if (t == 0) {
        int tot = 0;
#pragma unroll
        for (int w = 0; w < 8; w++) tot += wsum[w];
        g_bsum[blockIdx.x] = tot;
    }
}

// scan_offsets computes its own block prefix from g_bsum (scan_tops folded in).
// Pure read of prior-kernel output in the same stream — no race.
__global__ void scan_offsets_kernel() {
    __shared__ int wtot[8];
    __shared__ int bpref_sh;
    int t = threadIdx.x;
    int lane = t & 31, warp = t >> 5;
    {
        int v = (t < blockIdx.x && t < SCAN_BLOCKS) ? g_bsum[t] : 0;
#pragma unroll
        for (int off = 16; off > 0; off >>= 1) v += __shfl_xor_sync(0xffffffffu, v, off);
        if (lane == 0) wtot[warp] = v;
        __syncthreads();
        if (t == 0) {
            int run = 0;
#pragma unroll
            for (int w = 0; w < 8; w++) run += wtot[w];
            bpref_sh = run;
        }
        __syncthreads();
    }
    int bpref = bpref_sh;
    __syncthreads();
    int base = blockIdx.x * SCAN_ELEMS_PER_BLOCK + t * 4;
    int d[4];
    int tsum = 0;
#pragma unroll
    for (int j = 0; j < 4; j++) {
        int i = base + j;
        d[j] = (i < N_TX) ? g_deg[i] : 0;
        tsum += d[j];
    }
    int inc = tsum;
#pragma unroll
    for (int off = 1; off < 32; off <<= 1) {
        int v = __shfl_up_sync(0xffffffffu, inc, off);
        if (lane >= off) inc += v;
    }
    if (lane == 31) wtot[warp] = inc;
    __syncthreads();
    if (t == 0) {
        int run = 0;
#pragma unroll
        for (int w = 0; w < 8; w++) { int v = wtot[w]; wtot[w] = run; run += v; }
    }
    __syncthreads();
    int wpref = wtot[warp];
    int run = bpref + wpref + (inc - tsum);
#pragma unroll
    for (int j = 0; j < 4; j++) {
        int i = base + j;
        if (i < N_TX) { g_off[i] = run; g_woff[i] = run; run += d[j]; }
    }
}

__global__ void fill_kernel(const int* __restrict__ edge) {
    int e = blockIdx.x * blockDim.x + threadIdx.x;
    if (e >= E_NUM) return;
    int dst = edge[E_NUM + e];
    int pos = atomicAdd(&g_woff[dst], 1);
    g_csr_src[pos] = edge[e];
}

// ---------------- kernel 5: gather-aggregate + fused pool, fp16 z -------------------
__global__ void aggregate_kernel(const int* __restrict__ batch_tx) {
    int gtid = blockIdx.x * blockDim.x + threadIdx.x;
    int w = gtid >> 5;
    int lane = gtid & 31;
    int d0 = w * 4;
    if (d0 >= N_TX) return;
    int dend = d0 + 4; if (dend > N_TX) dend = N_TX;
    int h = lane >> 3;
    float p0 = 0.f, p1 = 0.f;
    int cur = -1;
    for (int d = d0; d < dend; d++) {
        int beg = g_off[d], end = g_off[d + 1];
        float4 ad4 = __ldg((const float4*)&g_alpha_dst[d * 4]);
        float ad = (h == 0) ? ad4.x : (h == 1) ? ad4.y : (h == 2) ? ad4.z : ad4.w;
        float ax = 0.f, ay = 0.f, s = 0.f;
        int i = beg;
        for (; i + 4 <= end; i += 4) {
            int sA = __ldg(&g_csr_src[i + 0]);
            int sB = __ldg(&g_csr_src[i + 1]);
            int sC = __ldg(&g_csr_src[i + 2]);
            int sD = __ldg(&g_csr_src[i + 3]);
            float4 aA = __ldg((const float4*)&g_alpha_src[sA * 4]);
            float4 aB = __ldg((const float4*)&g_alpha_src[sB * 4]);
            float4 aC = __ldg((const float4*)&g_alpha_src[sC * 4]);
            float4 aD = __ldg((const float4*)&g_alpha_src[sD * 4]);
            __half2 zA = __ldg((const __half2*)&g_z_half[sA * 64 + 2 * lane]);
            __half2 zB = __ldg((const __half2*)&g_z_half[sB * 64 + 2 * lane]);
            __half2 zC = __ldg((const __half2*)&g_z_half[sC * 64 + 2 * lane]);
            __half2 zD = __ldg((const __half2*)&g_z_half[sD * 64 + 2 * lane]);
            float eA = __expf(leaky(((h == 0) ? aA.x : (h == 1) ? aA.y : (h == 2) ? aA.z : aA.w) + ad));
            float eB = __expf(leaky(((h == 0) ? aB.x : (h == 1) ? aB.y : (h == 2) ? aB.z : aB.w) + ad));
            float eC = __expf(leaky(((h == 0) ? aC.x : (h == 1) ? aC.y : (h == 2) ? aC.z : aC.w) + ad));
            float eD = __expf(leaky(((h == 0) ? aD.x : (h == 1) ? aD.y : (h == 2) ? aD.z : aD.w) + ad));
            float2 fA = __half22float2(zA);
            float2 fB = __half22float2(zB);
            float2 fC = __half22float2(zC);
            float2 fD = __half22float2(zD);
            s += (eA + eB) + (eC + eD);
            ax = fmaf(eA, fA.x, fmaf(eB, fB.x, fmaf(eC, fC.x, fmaf(eD, fD.x, ax))));
            ay = fmaf(eA, fA.y, fmaf(eB, fB.y, fmaf(eC, fC.y, fmaf(eD, fD.y, ay))));
        }
        for (; i < end; i++) {
            int src = __ldg(&g_csr_src[i]);
            float4 a4 = __ldg((const float4*)&g_alpha_src[src * 4]);
            float as = (h == 0) ? a4.x : (h == 1) ? a4.y : (h == 2) ? a4.z : a4.w;
            float e = __expf(leaky(as + ad));
            __half2 z = __ldg((const __half2*)&g_z_half[src * 64 + 2 * lane]);
            float2 f = __half22float2(z);
            s += e;
            ax = fmaf(e, f.x, ax);
            ay = fmaf(e, f.y, ay);
        }
        float inv = 1.0f / (s + 1e-16f);
        float o0 = fmaxf(ax * inv, 0.f);
        float o1 = fmaxf(ay * inv, 0.f);
        int b = __ldg(&batch_tx[d]);
        if (b != cur) {
            if (cur >= 0) red_add_v2(&g_pool[cur * 64 + 2 * lane], make_float2(p0, p1));
            cur = b; p0 = 0.f; p1 = 0.f;
        }
        p0 += o0; p1 += o1;
    }
    if (cur >= 0) red_add_v2(&g_pool[cur * 64 + 2 * lane], make_float2(p0, p1));
}

// ---------------- kernel 6: classifier MLP ------------------------------------------
__global__ void final_kernel(const float* __restrict__ W_c1, const float* __restrict__ b_c1,
                             const float* __restrict__ W_c2, const float* __restrict__ b_c2,
                             float* __restrict__ out) {
    int g = threadIdx.x;
    if (g >= G_NUM) return;
    float inv = 1.0f / fmaxf(g_cnt[g], 1.0f);
    float feat[64];
#pragma unroll
    for (int c = 0; c < 64; c++) feat[c] = g_pool[g * 64 + c] * inv;
    float o = b_c2[0];
#pragma unroll 4
    for (int j = 0; j < 32; j++) {
        float hsum = b_c1[j];
#pragma unroll
        for (int c = 0; c < 64; c++) hsum += feat[c] * W_c1[c * 32 + j];
        o += fmaxf(hsum, 0.f) * W_c2[j];
    }
    out[g] = o;
}

// ---------------- launch ------------------------------------------------------------
extern "C" void kernel_launch(void* const* d_in, const int* in_sizes, int n_in,
                              void* d_out, int out_size) {
    const float* x_tx       = (const float*)d_in[0];
    const float* x_addr     = (const float*)d_in[1];
    const float* W_proj_tx  = (const float*)d_in[2];
    const float* b_proj_tx  = (const float*)d_in[3];
    const float* W_proj_addr= (const float*)d_in[4];
    const float* b_proj_addr= (const float*)d_in[5];
    const float* W_han_tx   = (const float*)d_in[6];
    const float* b_han_tx   = (const float*)d_in[7];
    const float* W_han_addr = (const float*)d_in[8];
    const float* b_han_addr = (const float*)d_in[9];
    const float* att_src_at = (const float*)d_in[12];
    const float* att_dst_at = (const float*)d_in[13];
    const float* W_c1       = (const float*)d_in[17];
    const float* b_c1       = (const float*)d_in[18];
    const float* W_c2       = (const float*)d_in[19];
    const float* b_c2       = (const float*)d_in[20];
    const int*   edge_at    = (const int*)d_in[22];
    const int*   batch_tx   = (const int*)d_in[23];
    float* out = (float*)d_out;

    static cudaStream_t s2 = nullptr;
    static cudaEvent_t ev_fork = nullptr, ev_csr = nullptr;
    if (!s2) {
        cudaStreamCreateWithFlags(&s2, cudaStreamNonBlocking);
        cudaEventCreateWithFlags(&ev_fork, cudaEventDisableTiming);
        cudaEventCreateWithFlags(&ev_csr, cudaEventDisableTiming);
    }

    // fork
    cudaEventRecord(ev_fork, 0);
    cudaStreamWaitEvent(s2, ev_fork, 0);

    // enqueue order chosen so addr_gemm is the 6th launch (ncu -s 5 -c 1 captures it)
    prep_kernel<<<1, 256>>>(W_proj_tx, b_proj_tx, W_proj_addr, b_proj_addr,
                            W_han_tx, b_han_tx, W_han_addr, b_han_addr, att_dst_at);        // 1
    tx_alpha_kernel<<<(N_TX * 32 + 255) / 256, 256>>>(x_tx);                                 // 2
    init_kernel<<<(N_TX + 255) / 256, 256, 0, s2>>>();                                       // 3
    hist_kernel<<<(E_NUM + 255) / 256, 256, 0, s2>>>(edge_at);                               // 4
    cnt_kernel<<<98, 256, 0, s2>>>(batch_tx);                                                // 5
    addr_gemm_kernel<<<(N_ADDR + 127) / 128, 256>>>(x_addr, att_src_at);                     // 6 <- profiled
    scan_sum_kernel<<<SCAN_BLOCKS, 256, 0, s2>>>();                                          // 7
    scan_offsets_kernel<<<SCAN_BLOCKS, 256, 0, s2>>>();                                      // 8
    fill_kernel<<<(E_NUM + 255) / 256, 256, 0, s2>>>(edge_at);                               // 9
    cudaEventRecord(ev_csr, s2);

    cudaStreamWaitEvent(0, ev_csr, 0);
    aggregate_kernel<<<((N_TX + 3) / 4 * 32 + 255) / 256, 256>>>(batch_tx);                  // 10
    final_kernel<<<1, 128>>>(W_c1, b_c1, W_c2, b_c2, out);                                   // 11
}

// round 16
// speedup vs baseline: 1.4404x; 1.4404x over previous
#include <cuda_runtime.h>
#include <cuda_fp16.h>
#include <math.h>

#define N_TX   100000
#define N_ADDR 100000
#define E_NUM  1000000
#define G_NUM  128

#define SCAN_ELEMS_PER_BLOCK 1024
#define SCAN_BLOCKS ((N_TX + SCAN_ELEMS_PER_BLOCK - 1) / SCAN_ELEMS_PER_BLOCK)  // 98

// ---------------- scratch ----------------------------------------------------------
__device__ float g_At[64 * 68];
__device__ float g_b_addr[64];
__device__ float g_U_tx[65 * 4];
__device__ float g_v_tx[4];
__device__ __half g_z_half[N_ADDR * 64];   // z_addr in fp16 (accumulation stays fp32)
__device__ float g_alpha_src[N_ADDR * 4];
__device__ float g_alpha_dst[N_TX * 4];
__device__ float g_pool[G_NUM * 64];
__device__ float g_cnt[G_NUM];
// CSR scratch
__device__ int g_deg[N_TX];
__device__ int g_off[N_TX + 1];
__device__ int g_woff[N_TX];
__device__ int g_csr_src[E_NUM];
__device__ int g_bsum[SCAN_BLOCKS];

__device__ __forceinline__ float leaky(float x) { return x > 0.f ? x : 0.2f * x; }

__device__ __forceinline__ void red_add_v2(float* addr, float2 v) {
    asm volatile("red.global.add.v2.f32 [%0], {%1, %2};"
                 :: "l"(addr), "f"(v.x), "f"(v.y) : "memory");
}

// ---------------- kernel 1: fold weights -------------------------------------------
__global__ void prep_kernel(const float* __restrict__ Wp_tx, const float* __restrict__ bp_tx,
                            const float* __restrict__ Wp_addr, const float* __restrict__ bp_addr,
                            const float* __restrict__ Wh_tx, const float* __restrict__ bh_tx,
                            const float* __restrict__ Wh_addr, const float* __restrict__ bh_addr,
                            const float* __restrict__ att_dst_at) {
    __shared__ float t[64 * 4];
    int tid = threadIdx.x;
    for (int idx = tid; idx < 64 * 4; idx += blockDim.x) {
        int j = idx >> 2, h = idx & 3;
        float s = 0.f;
        for (int d = 0; d < 16; d++) s += Wh_tx[j * 64 + h * 16 + d] * att_dst_at[h * 16 + d];
        t[j * 4 + h] = s;
    }
    __syncthreads();
    for (int idx = tid; idx < 65 * 4; idx += blockDim.x) {
        int k = idx >> 2, h = idx & 3;
        float s = 0.f;
        for (int j = 0; j < 64; j++) s += Wp_tx[k * 64 + j] * t[j * 4 + h];
        g_U_tx[k * 4 + h] = s;
    }
    if (tid < 4) {
        int h = tid;
        float s = 0.f;
        for (int j = 0; j < 64; j++) s += bp_tx[j] * t[j * 4 + h];
        for (int d = 0; d < 16; d++) s += bh_tx[h * 16 + d] * att_dst_at[h * 16 + d];
        g_v_tx[h] = s;
    }
    for (int idx = tid; idx < 65 * 64; idx += blockDim.x) {
        int k = idx >> 6, c = idx & 63;
        float s = 0.f;
        for (int j = 0; j < 64; j++) s += Wp_addr[k * 64 + j] * Wh_addr[j * 64 + c];
        g_At[c * 68 + k] = s;
    }
    for (int i = tid; i < 64 * 3; i += blockDim.x)
        g_At[(i / 3) * 68 + 65 + (i % 3)] = 0.f;
    for (int c = tid; c < 64; c += blockDim.x) {
        float s = bh_addr[c];
        for (int j = 0; j < 64; j++) s += bp_addr[j] * Wh_addr[j * 64 + c];
        g_b_addr[c] = s;
    }
}

// ---------------- kernel 2: init (zeroing only) --------------------------------------
__global__ void init_kernel() {
    int i = blockIdx.x * blockDim.x + threadIdx.x;
    if (i < N_TX) g_deg[i] = 0;
    if (i < G_NUM * 64) g_pool[i] = 0.f;
    if (i < G_NUM) g_cnt[i] = 0.f;
    if (i == 0) g_off[N_TX] = E_NUM;
}

// ---------------- cnt: per-graph node counts (after init, same stream) ---------------
__global__ void cnt_kernel(const int* __restrict__ batch_tx) {
    __shared__ int loc[G_NUM];
    int t = threadIdx.x;
    if (t < G_NUM) loc[t] = 0;
    __syncthreads();
    for (int i = blockIdx.x * blockDim.x + t; i < N_TX; i += gridDim.x * blockDim.x)
        atomicAdd(&loc[batch_tx[i]], 1);
    __syncthreads();
    if (t < G_NUM && loc[t] > 0) atomicAdd(&g_cnt[t], (float)loc[t]);
}

// ---------------- kernel 3: alpha_dst (warp per tx node) ---------------------------
__global__ void tx_alpha_kernel(const float* __restrict__ x_tx) {
    __shared__ float U[65 * 4];
    __shared__ float v[4];
    int tid = threadIdx.x;
    for (int i = tid; i < 65 * 4; i += blockDim.x) U[i] = g_U_tx[i];
    if (tid < 4) v[tid] = g_v_tx[tid];
    __syncthreads();
    int warp = (blockIdx.x * blockDim.x + tid) >> 5;
    int lane = tid & 31;
    if (warp >= N_TX) return;
    const float* xr = x_tx + (long long)warp * 65;
    float x0 = xr[lane];
    float x1 = xr[32 + lane];
    float x2 = (lane == 0) ? xr[64] : 0.f;
#pragma unroll
    for (int h = 0; h < 4; h++) {
        float p = x0 * U[lane * 4 + h] + x1 * U[(32 + lane) * 4 + h] + x2 * U[64 * 4 + h];
#pragma unroll
        for (int off = 16; off > 0; off >>= 1) p += __shfl_xor_sync(0xffffffffu, p, off);
        if (lane == h) g_alpha_dst[warp * 4 + h] = p + v[h];
    }
}

// ---------------- kernel 4: z_addr GEMM, A in registers, fp16 z stores --------------
__global__ void __launch_bounds__(256) addr_gemm_kernel(const float* __restrict__ x_addr,
                                                        const float* __restrict__ att_src_at) {
    __shared__ float xs[32][68];
    __shared__ float bs[64];
    __shared__ float att[64];
    int tid = threadIdx.x;
    int col = tid & 63, y = tid >> 6;
    float4 a[17];
    const float4* ap = (const float4*)&g_At[col * 68];
#pragma unroll
    for (int i = 0; i < 17; i++) a[i] = ap[i];
    if (tid < 64) { bs[tid] = g_b_addr[tid]; att[tid] = att_src_at[tid]; }
    for (int i = tid; i < 32 * 3; i += 256) xs[i / 3][65 + (i % 3)] = 0.f;
    __syncthreads();

    int base = blockIdx.x * 128;
#pragma unroll 1
    for (int t = 0; t < 4; t++) {
        int tile0 = base + t * 32;
        for (int i = tid; i < 32 * 65; i += 256) {
            int n = i / 65, k = i - n * 65;
            int node = tile0 + n;
            xs[n][k] = (node < N_ADDR) ? x_addr[(long long)node * 65 + k] : 0.f;
        }
        __syncthreads();
        float acc[8];
#pragma unroll
        for (int n = 0; n < 8; n++) acc[n] = bs[col];
#pragma unroll
        for (int k4 = 0; k4 < 17; k4++) {
            float4 av = a[k4];
#pragma unroll
            for (int n = 0; n < 8; n++) {
                float4 xv = *(const float4*)&xs[y * 8 + n][k4 * 4];
                acc[n] += xv.x * av.x + xv.y * av.y + xv.z * av.z + xv.w * av.w;
            }
        }
#pragma unroll
        for (int n = 0; n < 8; n++) {
            int node = tile0 + y * 8 + n;
            if (node < N_ADDR) {
                g_z_half[node * 64 + col] = __float2half_rn(acc[n]);
                float p = acc[n] * att[col];
#pragma unroll
                for (int off = 8; off > 0; off >>= 1) p += __shfl_xor_sync(0xffffffffu, p, off);
                if ((col & 15) == 0) g_alpha_src[node * 4 + (col >> 4)] = p;
            }
        }
        __syncthreads();
    }
}

// ---------------- CSR build ---------------------------------------------------------
__global__ void hist_kernel(const int* __restrict__ edge) {
    int e = blockIdx.x * blockDim.x + threadIdx.x;
    if (e >= E_NUM) return;
    atomicAdd(&g_deg[edge[E_NUM + e]], 1);
}

__global__ void scan_sum_kernel() {
    __shared__ int wsum[8];
    int t = threadIdx.x;
    int base = blockIdx.x * SCAN_ELEMS_PER_BLOCK + t * 4;
    int s = 0;
#pragma unroll
    for (int j = 0; j < 4; j++) {
        int i = base + j;
        if (i < N_TX) s += g_deg[i];
    }
#pragma unroll
    for (int off = 16; off > 0; off >>= 1) s += __shfl_xor_sync(0xffffffffu, s, off);
    if ((t & 31) == 0) wsum[t >> 5] = s;
    __syncthreads();
    if (t == 0) {
        int tot = 0;
#pragma unroll
        for (int w = 0; w < 8; w++) tot += wsum[w];
        g_bsum[blockIdx.x] = tot;
    }
}

// scan_offsets computes its own block prefix from g_bsum (scan_tops folded in).
__global__ void scan_offsets_kernel() {
    __shared__ int wtot[8];
    __shared__ int bpref_sh;
    int t = threadIdx.x;
    int lane = t & 31, warp = t >> 5;
    {
        int v = (t < blockIdx.x && t < SCAN_BLOCKS) ? g_bsum[t] : 0;
#pragma unroll
        for (int off = 16; off > 0; off >>= 1) v += __shfl_xor_sync(0xffffffffu, v, off);
        if (lane == 0) wtot[warp] = v;
        __syncthreads();
        if (t == 0) {
            int run = 0;
#pragma unroll
            for (int w = 0; w < 8; w++) run += wtot[w];
            bpref_sh = run;
        }
        __syncthreads();
    }
    int bpref = bpref_sh;
    __syncthreads();
    int base = blockIdx.x * SCAN_ELEMS_PER_BLOCK + t * 4;
    int d[4];
    int tsum = 0;
#pragma unroll
    for (int j = 0; j < 4; j++) {
        int i = base + j;
        d[j] = (i < N_TX) ? g_deg[i] : 0;
        tsum += d[j];
    }
    int inc = tsum;
#pragma unroll
    for (int off = 1; off < 32; off <<= 1) {
        int v = __shfl_up_sync(0xffffffffu, inc, off);
        if (lane >= off) inc += v;
    }
    if (lane == 31) wtot[warp] = inc;
    __syncthreads();
    if (t == 0) {
        int run = 0;
#pragma unroll
        for (int w = 0; w < 8; w++) { int v = wtot[w]; wtot[w] = run; run += v; }
    }
    __syncthreads();
    int wpref = wtot[warp];
    int run = bpref + wpref + (inc - tsum);
#pragma unroll
    for (int j = 0; j < 4; j++) {
        int i = base + j;
        if (i < N_TX) { g_off[i] = run; g_woff[i] = run; run += d[j]; }
    }
}

__global__ void fill_kernel(const int* __restrict__ edge) {
    int e = blockIdx.x * blockDim.x + threadIdx.x;
    if (e >= E_NUM) return;
    int dst = edge[E_NUM + e];
    int pos = atomicAdd(&g_woff[dst], 1);
    g_csr_src[pos] = edge[e];
}

// ---------------- kernel 5: gather-aggregate + fused pool, fp16 z -------------------
__global__ void aggregate_kernel(const int* __restrict__ batch_tx) {
    int gtid = blockIdx.x * blockDim.x + threadIdx.x;
    int w = gtid >> 5;
    int lane = gtid & 31;
    int d0 = w * 4;
    if (d0 >= N_TX) return;
    int dend = d0 + 4; if (dend > N_TX) dend = N_TX;
    int h = lane >> 3;
    float p0 = 0.f, p1 = 0.f;
    int cur = -1;
    for (int d = d0; d < dend; d++) {
        int beg = g_off[d], end = g_off[d + 1];
        float4 ad4 = __ldg((const float4*)&g_alpha_dst[d * 4]);
        float ad = (h == 0) ? ad4.x : (h == 1) ? ad4.y : (h == 2) ? ad4.z : ad4.w;
        float ax = 0.f, ay = 0.f, s = 0.f;
        int i = beg;
        for (; i + 4 <= end; i += 4) {
            int sA = __ldg(&g_csr_src[i + 0]);
            int sB = __ldg(&g_csr_src[i + 1]);
            int sC = __ldg(&g_csr_src[i + 2]);
            int sD = __ldg(&g_csr_src[i + 3]);
            float4 aA = __ldg((const float4*)&g_alpha_src[sA * 4]);
            float4 aB = __ldg((const float4*)&g_alpha_src[sB * 4]);
            float4 aC = __ldg((const float4*)&g_alpha_src[sC * 4]);
            float4 aD = __ldg((const float4*)&g_alpha_src[sD * 4]);
            __half2 zA = __ldg((const __half2*)&g_z_half[sA * 64 + 2 * lane]);
            __half2 zB = __ldg((const __half2*)&g_z_half[sB * 64 + 2 * lane]);
            __half2 zC = __ldg((const __half2*)&g_z_half[sC * 64 + 2 * lane]);
            __half2 zD = __ldg((const __half2*)&g_z_half[sD * 64 + 2 * lane]);
            float eA = __expf(leaky(((h == 0) ? aA.x : (h == 1) ? aA.y : (h == 2) ? aA.z : aA.w) + ad));
            float eB = __expf(leaky(((h == 0) ? aB.x : (h == 1) ? aB.y : (h == 2) ? aB.z : aB.w) + ad));
            float eC = __expf(leaky(((h == 0) ? aC.x : (h == 1) ? aC.y : (h == 2) ? aC.z : aC.w) + ad));
            float eD = __expf(leaky(((h == 0) ? aD.x : (h == 1) ? aD.y : (h == 2) ? aD.z : aD.w) + ad));
            float2 fA = __half22float2(zA);
            float2 fB = __half22float2(zB);
            float2 fC = __half22float2(zC);
            float2 fD = __half22float2(zD);
            s += (eA + eB) + (eC + eD);
            ax = fmaf(eA, fA.x, fmaf(eB, fB.x, fmaf(eC, fC.x, fmaf(eD, fD.x, ax))));
            ay = fmaf(eA, fA.y, fmaf(eB, fB.y, fmaf(eC, fC.y, fmaf(eD, fD.y, ay))));
        }
        for (; i < end; i++) {
            int src = __ldg(&g_csr_src[i]);
            float4 a4 = __ldg((const float4*)&g_alpha_src[src * 4]);
            float as = (h == 0) ? a4.x : (h == 1) ? a4.y : (h == 2) ? a4.z : a4.w;
            float e = __expf(leaky(as + ad));
            __half2 z = __ldg((const __half2*)&g_z_half[src * 64 + 2 * lane]);
            float2 f = __half22float2(z);
            s += e;
            ax = fmaf(e, f.x, ax);
            ay = fmaf(e, f.y, ay);
        }
        float inv = 1.0f / (s + 1e-16f);
        float o0 = fmaxf(ax * inv, 0.f);
        float o1 = fmaxf(ay * inv, 0.f);
        int b = __ldg(&batch_tx[d]);
        if (b != cur) {
            if (cur >= 0) red_add_v2(&g_pool[cur * 64 + 2 * lane], make_float2(p0, p1));
            cur = b; p0 = 0.f; p1 = 0.f;
        }
        p0 += o0; p1 += o1;
    }
    if (cur >= 0) red_add_v2(&g_pool[cur * 64 + 2 * lane], make_float2(p0, p1));
}

// ---------------- kernel 6: classifier MLP ------------------------------------------
__global__ void final_kernel(const float* __restrict__ W_c1, const float* __restrict__ b_c1,
                             const float* __restrict__ W_c2, const float* __restrict__ b_c2,
                             float* __restrict__ out) {
    int g = threadIdx.x;
    if (g >= G_NUM) return;
    float inv = 1.0f / fmaxf(g_cnt[g], 1.0f);
    float feat[64];
#pragma unroll
    for (int c = 0; c < 64; c++) feat[c] = g_pool[g * 64 + c] * inv;
    float o = b_c2[0];
#pragma unroll 4
    for (int j = 0; j < 32; j++) {
        float hsum = b_c1[j];
#pragma unroll
        for (int c = 0; c < 64; c++) hsum += feat[c] * W_c1[c * 32 + j];
        o += fmaxf(hsum, 0.f) * W_c2[j];
    }
    out[g] = o;
}

// ---------------- launch (R13 enqueue order: s2 chain first, then main chain) --------
extern "C" void kernel_launch(void* const* d_in, const int* in_sizes, int n_in,
                              void* d_out, int out_size) {
    const float* x_tx       = (const float*)d_in[0];
    const float* x_addr     = (const float*)d_in[1];
    const float* W_proj_tx  = (const float*)d_in[2];
    const float* b_proj_tx  = (const float*)d_in[3];
    const float* W_proj_addr= (const float*)d_in[4];
    const float* b_proj_addr= (const float*)d_in[5];
    const float* W_han_tx   = (const float*)d_in[6];
    const float* b_han_tx   = (const float*)d_in[7];
    const float* W_han_addr = (const float*)d_in[8];
    const float* b_han_addr = (const float*)d_in[9];
    const float* att_src_at = (const float*)d_in[12];
    const float* att_dst_at = (const float*)d_in[13];
    const float* W_c1       = (const float*)d_in[17];
    const float* b_c1       = (const float*)d_in[18];
    const float* W_c2       = (const float*)d_in[19];
    const float* b_c2       = (const float*)d_in[20];
    const int*   edge_at    = (const int*)d_in[22];
    const int*   batch_tx   = (const int*)d_in[23];
    float* out = (float*)d_out;

    static cudaStream_t s2 = nullptr;
    static cudaEvent_t ev_fork = nullptr, ev_csr = nullptr;
    if (!s2) {
        cudaStreamCreateWithFlags(&s2, cudaStreamNonBlocking);
        cudaEventCreateWithFlags(&ev_fork, cudaEventDisableTiming);
        cudaEventCreateWithFlags(&ev_csr, cudaEventDisableTiming);
    }

    // fork: CSR chain on s2, compute chain on main stream
    cudaEventRecord(ev_fork, 0);
    cudaStreamWaitEvent(s2, ev_fork, 0);

    // CSR chain (side stream) — enqueued first, exactly as in the 193.8us champion
    init_kernel<<<(N_TX + 255) / 256, 256, 0, s2>>>();
    hist_kernel<<<(E_NUM + 255) / 256, 256, 0, s2>>>(edge_at);
    cnt_kernel<<<98, 256, 0, s2>>>(batch_tx);
    scan_sum_kernel<<<SCAN_BLOCKS, 256, 0, s2>>>();
    scan_offsets_kernel<<<SCAN_BLOCKS, 256, 0, s2>>>();
    fill_kernel<<<(E_NUM + 255) / 256, 256, 0, s2>>>(edge_at);
    cudaEventRecord(ev_csr, s2);

    // compute chain (main stream)
    prep_kernel<<<1, 256>>>(W_proj_tx, b_proj_tx, W_proj_addr, b_proj_addr,
                            W_han_tx, b_han_tx, W_han_addr, b_han_addr, att_dst_at);
    tx_alpha_kernel<<<(N_TX * 32 + 255) / 256, 256>>>(x_tx);
    addr_gemm_kernel<<<(N_ADDR + 127) / 128, 256>>>(x_addr, att_src_at);

    // join, then aggregate (+fused pool) + classifier
    cudaStreamWaitEvent(0, ev_csr, 0);
    aggregate_kernel<<<((N_TX + 3) / 4 * 32 + 255) / 256, 256>>>(batch_tx);
    final_kernel<<<1, 128>>>(W_c1, b_c1, W_c2, b_c2, out);
}

// round 17
// speedup vs baseline: 1.5848x; 1.1003x over previous
#include <cuda_runtime.h>
#include <cuda_fp16.h>
#include <math.h>

#define N_TX   100000
#define N_ADDR 100000
#define E_NUM  1000000
#define G_NUM  128

#define SCAN_ELEMS_PER_BLOCK 1024
#define SCAN_BLOCKS ((N_TX + SCAN_ELEMS_PER_BLOCK - 1) / SCAN_ELEMS_PER_BLOCK)  // 98

// ---------------- scratch ----------------------------------------------------------
__device__ float g_At[64 * 68];
__device__ float g_b_addr[64];
__device__ float g_U_tx[65 * 4];
__device__ float g_v_tx[4];
__device__ __half g_z_half[N_ADDR * 64];   // z_addr in fp16 (accumulation stays fp32)
__device__ float g_alpha_src[N_ADDR * 4];
__device__ float g_alpha_dst[N_TX * 4];
__device__ float g_pool[G_NUM * 64];
__device__ float g_cnt[G_NUM];
// CSR scratch
__device__ int g_deg[N_TX];
__device__ int g_off[N_TX + 1];
__device__ int g_woff[N_TX];
__device__ int g_csr_src[E_NUM];
__device__ int g_bsum[SCAN_BLOCKS];
__device__ int g_bpref[SCAN_BLOCKS];

__device__ __forceinline__ float leaky(float x) { return x > 0.f ? x : 0.2f * x; }

__device__ __forceinline__ void red_add_v2(float* addr, float2 v) {
    asm volatile("red.global.add.v2.f32 [%0], {%1, %2};"
                 :: "l"(addr), "f"(v.x), "f"(v.y) : "memory");
}

// ---------------- kernel 1: fold weights (MULTI-BLOCK: grid=8) ----------------------
// block 0: t -> U_tx, v_tx (+ A_addr pad writes). block 1: b_addr.
// all 8 blocks: disjoint slices of the 65x64 A_addr dots. No cross-block deps.
__global__ void prep_kernel(const float* __restrict__ Wp_tx, const float* __restrict__ bp_tx,
                            const float* __restrict__ Wp_addr, const float* __restrict__ bp_addr,
                            const float* __restrict__ Wh_tx, const float* __restrict__ bh_tx,
                            const float* __restrict__ Wh_addr, const float* __restrict__ bh_addr,
                            const float* __restrict__ att_dst_at) {
    __shared__ float t[64 * 4];
    int tid = threadIdx.x;
    int bid = blockIdx.x;

    if (bid == 0) {
        for (int idx = tid; idx < 64 * 4; idx += blockDim.x) {
            int j = idx >> 2, h = idx & 3;
            float s = 0.f;
            for (int d = 0; d < 16; d++) s += Wh_tx[j * 64 + h * 16 + d] * att_dst_at[h * 16 + d];
            t[j * 4 + h] = s;
        }
        __syncthreads();
        for (int idx = tid; idx < 65 * 4; idx += blockDim.x) {
            int k = idx >> 2, h = idx & 3;
            float s = 0.f;
            for (int j = 0; j < 64; j++) s += Wp_tx[k * 64 + j] * t[j * 4 + h];
            g_U_tx[k * 4 + h] = s;
        }
        if (tid < 4) {
            int h = tid;
            float s = 0.f;
            for (int j = 0; j < 64; j++) s += bp_tx[j] * t[j * 4 + h];
            for (int d = 0; d < 16; d++) s += bh_tx[h * 16 + d] * att_dst_at[h * 16 + d];
            g_v_tx[h] = s;
        }
        for (int i = tid; i < 64 * 3; i += blockDim.x)
            g_At[(i / 3) * 68 + 65 + (i % 3)] = 0.f;   // zero-pad
    }
    if (bid == 1) {
        for (int c = tid; c < 64; c += blockDim.x) {
            float s = bh_addr[c];
            for (int j = 0; j < 64; j++) s += bp_addr[j] * Wh_addr[j * 64 + c];
            g_b_addr[c] = s;
        }
    }
    // all blocks: A_addr slices (65*64 = 4160 dots over 8 blocks x 256 threads)
    for (int idx = bid * blockDim.x + tid; idx < 65 * 64; idx += gridDim.x * blockDim.x) {
        int k = idx >> 6, c = idx & 63;
        float s = 0.f;
        for (int j = 0; j < 64; j++) s += Wp_addr[k * 64 + j] * Wh_addr[j * 64 + c];
        g_At[c * 68 + k] = s;
    }
}

// ---------------- kernel 2: init (zeroing only) --------------------------------------
__global__ void init_kernel() {
    int i = blockIdx.x * blockDim.x + threadIdx.x;
    if (i < N_TX) g_deg[i] = 0;
    if (i < G_NUM * 64) g_pool[i] = 0.f;
    if (i < G_NUM) g_cnt[i] = 0.f;
    if (i == 0) g_off[N_TX] = E_NUM;
}

// ---------------- cnt: per-graph node counts (after init, same stream) ---------------
__global__ void cnt_kernel(const int* __restrict__ batch_tx) {
    __shared__ int loc[G_NUM];
    int t = threadIdx.x;
    if (t < G_NUM) loc[t] = 0;
    __syncthreads();
    for (int i = blockIdx.x * blockDim.x + t; i < N_TX; i += gridDim.x * blockDim.x)
        atomicAdd(&loc[batch_tx[i]], 1);
    __syncthreads();
    if (t < G_NUM && loc[t] > 0) atomicAdd(&g_cnt[t], (float)loc[t]);
}

// ---------------- kernel 3: alpha_dst (warp per tx node) ---------------------------
__global__ void tx_alpha_kernel(const float* __restrict__ x_tx) {
    __shared__ float U[65 * 4];
    __shared__ float v[4];
    int tid = threadIdx.x;
    for (int i = tid; i < 65 * 4; i += blockDim.x) U[i] = g_U_tx[i];
    if (tid < 4) v[tid] = g_v_tx[tid];
    __syncthreads();
    int warp = (blockIdx.x * blockDim.x + tid) >> 5;
    int lane = tid & 31;
    if (warp >= N_TX) return;
    const float* xr = x_tx + (long long)warp * 65;
    float x0 = xr[lane];
    float x1 = xr[32 + lane];
    float x2 = (lane == 0) ? xr[64] : 0.f;
#pragma unroll
    for (int h = 0; h < 4; h++) {
        float p = x0 * U[lane * 4 + h] + x1 * U[(32 + lane) * 4 + h] + x2 * U[64 * 4 + h];
#pragma unroll
        for (int off = 16; off > 0; off >>= 1) p += __shfl_xor_sync(0xffffffffu, p, off);
        if (lane == h) g_alpha_dst[warp * 4 + h] = p + v[h];
    }
}

// ---------------- kernel 4: z_addr GEMM, A in registers, fp16 z stores --------------
__global__ void __launch_bounds__(256) addr_gemm_kernel(const float* __restrict__ x_addr,
                                                        const float* __restrict__ att_src_at) {
    __shared__ float xs[32][68];
    __shared__ float bs[64];
    __shared__ float att[64];
    int tid = threadIdx.x;
    int col = tid & 63, y = tid >> 6;
    float4 a[17];
    const float4* ap = (const float4*)&g_At[col * 68];
#pragma unroll
    for (int i = 0; i < 17; i++) a[i] = ap[i];
    if (tid < 64) { bs[tid] = g_b_addr[tid]; att[tid] = att_src_at[tid]; }
    for (int i = tid; i < 32 * 3; i += 256) xs[i / 3][65 + (i % 3)] = 0.f;
    __syncthreads();

    int base = blockIdx.x * 128;
#pragma unroll 1
    for (int t = 0; t < 4; t++) {
        int tile0 = base + t * 32;
        for (int i = tid; i < 32 * 65; i += 256) {
            int n = i / 65, k = i - n * 65;
            int node = tile0 + n;
            xs[n][k] = (node < N_ADDR) ? x_addr[(long long)node * 65 + k] : 0.f;
        }
        __syncthreads();
        float acc[8];
#pragma unroll
        for (int n = 0; n < 8; n++) acc[n] = bs[col];
#pragma unroll
        for (int k4 = 0; k4 < 17; k4++) {
            float4 av = a[k4];
#pragma unroll
            for (int n = 0; n < 8; n++) {
                float4 xv = *(const float4*)&xs[y * 8 + n][k4 * 4];
                acc[n] += xv.x * av.x + xv.y * av.y + xv.z * av.z + xv.w * av.w;
            }
        }
#pragma unroll
        for (int n = 0; n < 8; n++) {
            int node = tile0 + y * 8 + n;
            if (node < N_ADDR) {
                g_z_half[node * 64 + col] = __float2half_rn(acc[n]);
                float p = acc[n] * att[col];
#pragma unroll
                for (int off = 8; off > 0; off >>= 1) p += __shfl_xor_sync(0xffffffffu, p, off);
                if ((col & 15) == 0) g_alpha_src[node * 4 + (col >> 4)] = p;
            }
        }
        __syncthreads();
    }
}

// ---------------- CSR build ---------------------------------------------------------
__global__ void hist_kernel(const int* __restrict__ edge) {
    int e = blockIdx.x * blockDim.x + threadIdx.x;
    if (e >= E_NUM) return;
    atomicAdd(&g_deg[edge[E_NUM + e]], 1);
}

__global__ void scan_sum_kernel() {
    __shared__ int wsum[8];
    int t = threadIdx.x;
    int base = blockIdx.x * SCAN_ELEMS_PER_BLOCK + t * 4;
    int s = 0;
#pragma unroll
    for (int j = 0; j < 4; j++) {
        int i = base + j;
        if (i < N_TX) s += g_deg[i];
    }
#pragma unroll
    for (int off = 16; off > 0; off >>= 1) s += __shfl_xor_sync(0xffffffffu, s, off);
    if ((t & 31) == 0) wsum[t >> 5] = s;
    __syncthreads();
    if (t == 0) {
        int tot = 0;
#pragma unroll
        for (int w = 0; w < 8; w++) tot += wsum[w];
        g_bsum[blockIdx.x] = tot;
    }
}

__global__ void scan_tops_kernel() {
    __shared__ int sh[SCAN_BLOCKS];
    int t = threadIdx.x;
    if (t < SCAN_BLOCKS) sh[t] = g_bsum[t];
    __syncthreads();
    if (t == 0) {
        int run = 0;
        for (int i = 0; i < SCAN_BLOCKS; i++) { int v = sh[i]; sh[i] = run; run += v; }
    }
    __syncthreads();
    if (t < SCAN_BLOCKS) g_bpref[t] = sh[t];
}

__global__ void scan_offsets_kernel() {
    __shared__ int wtot[8];
    int t = threadIdx.x;
    int lane = t & 31, warp = t >> 5;
    int base = blockIdx.x * SCAN_ELEMS_PER_BLOCK + t * 4;
    int d[4];
    int tsum = 0;
#pragma unroll
    for (int j = 0; j < 4; j++) {
        int i = base + j;
        d[j] = (i < N_TX) ? g_deg[i] : 0;
        tsum += d[j];
    }
    int inc = tsum;
#pragma unroll
    for (int off = 1; off < 32; off <<= 1) {
        int v = __shfl_up_sync(0xffffffffu, inc, off);
        if (lane >= off) inc += v;
    }
    if (lane == 31) wtot[warp] = inc;
    __syncthreads();
    if (t == 0) {
        int run = 0;
#pragma unroll
        for (int w = 0; w < 8; w++) { int v = wtot[w]; wtot[w] = run; run += v; }
    }
    __syncthreads();
    int wpref = wtot[warp];
    int run = g_bpref[blockIdx.x] + wpref + (inc - tsum);
#pragma unroll
    for (int j = 0; j < 4; j++) {
        int i = base + j;
        if (i < N_TX) { g_off[i] = run; g_woff[i] = run; run += d[j]; }
    }
}

__global__ void fill_kernel(const int* __restrict__ edge) {
    int e = blockIdx.x * blockDim.x + threadIdx.x;
    if (e >= E_NUM) return;
    int dst = edge[E_NUM + e];
    int pos = atomicAdd(&g_woff[dst], 1);
    g_csr_src[pos] = edge[e];
}

// ---------------- kernel 5: gather-aggregate + fused pool, fp16 z -------------------
__global__ void aggregate_kernel(const int* __restrict__ batch_tx) {
    int gtid = blockIdx.x * blockDim.x + threadIdx.x;
    int w = gtid >> 5;
    int lane = gtid & 31;
    int d0 = w * 4;
    if (d0 >= N_TX) return;
    int dend = d0 + 4; if (dend > N_TX) dend = N_TX;
    int h = lane >> 3;
    float p0 = 0.f, p1 = 0.f;
    int cur = -1;
    for (int d = d0; d < dend; d++) {
        int beg = g_off[d], end = g_off[d + 1];
        float4 ad4 = __ldg((const float4*)&g_alpha_dst[d * 4]);
        float ad = (h == 0) ? ad4.x : (h == 1) ? ad4.y : (h == 2) ? ad4.z : ad4.w;
        float ax = 0.f, ay = 0.f, s = 0.f;
        int i = beg;
        for (; i + 4 <= end; i += 4) {
            int sA = __ldg(&g_csr_src[i + 0]);
            int sB = __ldg(&g_csr_src[i + 1]);
            int sC = __ldg(&g_csr_src[i + 2]);
            int sD = __ldg(&g_csr_src[i + 3]);
            float4 aA = __ldg((const float4*)&g_alpha_src[sA * 4]);
            float4 aB = __ldg((const float4*)&g_alpha_src[sB * 4]);
            float4 aC = __ldg((const float4*)&g_alpha_src[sC * 4]);
            float4 aD = __ldg((const float4*)&g_alpha_src[sD * 4]);
            __half2 zA = __ldg((const __half2*)&g_z_half[sA * 64 + 2 * lane]);
            __half2 zB = __ldg((const __half2*)&g_z_half[sB * 64 + 2 * lane]);
            __half2 zC = __ldg((const __half2*)&g_z_half[sC * 64 + 2 * lane]);
            __half2 zD = __ldg((const __half2*)&g_z_half[sD * 64 + 2 * lane]);
            float eA = __expf(leaky(((h == 0) ? aA.x : (h == 1) ? aA.y : (h == 2) ? aA.z : aA.w) + ad));
            float eB = __expf(leaky(((h == 0) ? aB.x : (h == 1) ? aB.y : (h == 2) ? aB.z : aB.w) + ad));
            float eC = __expf(leaky(((h == 0) ? aC.x : (h == 1) ? aC.y : (h == 2) ? aC.z : aC.w) + ad));
            float eD = __expf(leaky(((h == 0) ? aD.x : (h == 1) ? aD.y : (h == 2) ? aD.z : aD.w) + ad));
            float2 fA = __half22float2(zA);
            float2 fB = __half22float2(zB);
            float2 fC = __half22float2(zC);
            float2 fD = __half22float2(zD);
            s += (eA + eB) + (eC + eD);
            ax = fmaf(eA, fA.x, fmaf(eB, fB.x, fmaf(eC, fC.x, fmaf(eD, fD.x, ax))));
            ay = fmaf(eA, fA.y, fmaf(eB, fB.y, fmaf(eC, fC.y, fmaf(eD, fD.y, ay))));
        }
        for (; i < end; i++) {
            int src = __ldg(&g_csr_src[i]);
            float4 a4 = __ldg((const float4*)&g_alpha_src[src * 4]);
            float as = (h == 0) ? a4.x : (h == 1) ? a4.y : (h == 2) ? a4.z : a4.w;
            float e = __expf(leaky(as + ad));
            __half2 z = __ldg((const __half2*)&g_z_half[src * 64 + 2 * lane]);
            float2 f = __half22float2(z);
            s += e;
            ax = fmaf(e, f.x, ax);
            ay = fmaf(e, f.y, ay);
        }
        float inv = 1.0f / (s + 1e-16f);
        float o0 = fmaxf(ax * inv, 0.f);
        float o1 = fmaxf(ay * inv, 0.f);
        int b = __ldg(&batch_tx[d]);
        if (b != cur) {
            if (cur >= 0) red_add_v2(&g_pool[cur * 64 + 2 * lane], make_float2(p0, p1));
            cur = b; p0 = 0.f; p1 = 0.f;
        }
        p0 += o0; p1 += o1;
    }
    if (cur >= 0) red_add_v2(&g_pool[cur * 64 + 2 * lane], make_float2(p0, p1));
}

// ---------------- kernel 6: classifier MLP ------------------------------------------
__global__ void final_kernel(const float* __restrict__ W_c1, const float* __restrict__ b_c1,
                             const float* __restrict__ W_c2, const float* __restrict__ b_c2,
                             float* __restrict__ out) {
    int g = threadIdx.x;
    if (g >= G_NUM) return;
    float inv = 1.0f / fmaxf(g_cnt[g], 1.0f);
    float feat[64];
#pragma unroll
    for (int c = 0; c < 64; c++) feat[c] = g_pool[g * 64 + c] * inv;
    float o = b_c2[0];
#pragma unroll 4
    for (int j = 0; j < 32; j++) {
        float hsum = b_c1[j];
#pragma unroll
        for (int c = 0; c < 64; c++) hsum += feat[c] * W_c1[c * 32 + j];
        o += fmaxf(hsum, 0.f) * W_c2[j];
    }
    out[g] = o;
}

// ---------------- launch (R13 enqueue order: s2 chain first, then main chain) --------
extern "C" void kernel_launch(void* const* d_in, const int* in_sizes, int n_in,
                              void* d_out, int out_size) {
    const float* x_tx       = (const float*)d_in[0];
    const float* x_addr     = (const float*)d_in[1];
    const float* W_proj_tx  = (const float*)d_in[2];
    const float* b_proj_tx  = (const float*)d_in[3];
    const float* W_proj_addr= (const float*)d_in[4];
    const float* b_proj_addr= (const float*)d_in[5];
    const float* W_han_tx   = (const float*)d_in[6];
    const float* b_han_tx   = (const float*)d_in[7];
    const float* W_han_addr = (const float*)d_in[8];
    const float* b_han_addr = (const float*)d_in[9];
    const float* att_src_at = (const float*)d_in[12];
    const float* att_dst_at = (const float*)d_in[13];
    const float* W_c1       = (const float*)d_in[17];
    const float* b_c1       = (const float*)d_in[18];
    const float* W_c2       = (const float*)d_in[19];
    const float* b_c2       = (const float*)d_in[20];
    const int*   edge_at    = (const int*)d_in[22];
    const int*   batch_tx   = (const int*)d_in[23];
    float* out = (float*)d_out;

    static cudaStream_t s2 = nullptr;
    static cudaEvent_t ev_fork = nullptr, ev_csr = nullptr;
    if (!s2) {
        cudaStreamCreateWithFlags(&s2, cudaStreamNonBlocking);
        cudaEventCreateWithFlags(&ev_fork, cudaEventDisableTiming);
        cudaEventCreateWithFlags(&ev_csr, cudaEventDisableTiming);
    }

    // fork: CSR chain on s2, compute chain on main stream
    cudaEventRecord(ev_fork, 0);
    cudaStreamWaitEvent(s2, ev_fork, 0);

    // CSR chain (side stream) — enqueued first, exactly as in the 193.8us champion
    init_kernel<<<(N_TX + 255) / 256, 256, 0, s2>>>();
    hist_kernel<<<(E_NUM + 255) / 256, 256, 0, s2>>>(edge_at);
    cnt_kernel<<<98, 256, 0, s2>>>(batch_tx);
    scan_sum_kernel<<<SCAN_BLOCKS, 256, 0, s2>>>();
    scan_tops_kernel<<<1, 128, 0, s2>>>();
    scan_offsets_kernel<<<SCAN_BLOCKS, 256, 0, s2>>>();
    fill_kernel<<<(E_NUM + 255) / 256, 256, 0, s2>>>(edge_at);
    cudaEventRecord(ev_csr, s2);

    // compute chain (main stream) — multi-block prep shortens the chain head
    prep_kernel<<<8, 256>>>(W_proj_tx, b_proj_tx, W_proj_addr, b_proj_addr,
                            W_han_tx, b_han_tx, W_han_addr, b_han_addr, att_dst_at);
    tx_alpha_kernel<<<(N_TX * 32 + 255) / 256, 256>>>(x_tx);
    addr_gemm_kernel<<<(N_ADDR + 127) / 128, 256>>>(x_addr, att_src_at);

    // join, then aggregate (+fused pool) + classifier
    cudaStreamWaitEvent(0, ev_csr, 0);
    aggregate_kernel<<<((N_TX + 3) / 4 * 32 + 255) / 256, 256>>>(batch_tx);
    final_kernel<<<1, 128>>>(W_c1, b_c1, W_c2, b_c2, out);
}